// round 15
// baseline (speedup 1.0000x reference)
#include <cuda_runtime.h>

// Bilinear resample with zero-padding OOB corners.
// imgs: (B,1024,1024,1) f32, dvfs: (B,1024,1024,2) f32, out: (B,1024,1024,1) f32.
//
// Warp-column mapping: each warp owns 128 contiguous pixels; thread `lane`
// handles base + j*32 + lane for j=0..3. Every gather LDG spans 32 consecutive
// px (~2 cache lines -> few L1tex wavefronts) while each thread keeps 16
// independent gathers + 4 dvfs loads in flight (2x the outstanding misses of
// the 2px/thread version). Predicated @P gathers = exact zero-padding.

#define HH 1024
#define WW 1024
#define HW (HH * WW)

__device__ __forceinline__ float bilin_one(const float* __restrict__ img,
                                           int h, int w, float dx, float dy) {
    float fx = (float)w + dx;
    float fy = (float)h + dy;
    float x0f = floorf(fx);
    float y0f = floorf(fy);
    float wx = fx - x0f;
    float wy = fy - y0f;
    int x0 = (int)x0f;
    int y0 = (int)y0f;
    int x1 = x0 + 1;
    int y1 = y0 + 1;

    bool vx0 = (x0 >= 0) & (x0 < WW);
    bool vx1 = (x1 >= 0) & (x1 < WW);
    bool vy0 = (y0 >= 0) & (y0 < HH);
    bool vy1 = (y1 >= 0) & (y1 < HH);

    float v00 = 0.f, v01 = 0.f, v10 = 0.f, v11 = 0.f;
    if (vy0) {
        const float* row = img + (y0 << 10);
        if (vx0) v00 = __ldg(row + x0);
        if (vx1) v01 = __ldg(row + x1);
    }
    if (vy1) {
        const float* row = img + (y1 << 10);
        if (vx0) v10 = __ldg(row + x0);
        if (vx1) v11 = __ldg(row + x1);
    }

    float omx = 1.0f - wx;
    float omy = 1.0f - wy;
    float top = v00 * omx + v01 * wx;
    float bot = v10 * omx + v11 * wx;
    return top * omy + bot * wy;
}

__global__ void __launch_bounds__(256)
bilinear_kernel(const float* __restrict__ imgs,
                const float* __restrict__ dvfs,
                float* __restrict__ out,
                int total) {
    int t = blockIdx.x * blockDim.x + threadIdx.x;
    int lane = t & 31;
    int warp = t >> 5;
    int base = warp * 128;                 // 128 contiguous px per warp
    if (base >= total) return;

    // 4 independent coalesced dvfs loads (each LDG.64 covers 32 px window)
    const float2* dv = reinterpret_cast<const float2*>(dvfs);
    int i0 = base + lane;
    int i1 = i0 + 32;
    int i2 = i0 + 64;
    int i3 = i0 + 96;
    float2 d0 = __ldcs(dv + i0);
    float2 d1 = __ldcs(dv + i1);
    float2 d2 = __ldcs(dv + i2);
    float2 d3 = __ldcs(dv + i3);

    // Decode coordinates (all px of a warp window share b, h except at 1024-px
    // row boundaries which the general decode handles anyway).
    int w0 = i0 & (WW - 1), h0 = (i0 >> 10) & (HH - 1), b0 = i0 >> 20;
    int w1 = i1 & (WW - 1), h1 = (i1 >> 10) & (HH - 1), b1 = i1 >> 20;
    int w2 = i2 & (WW - 1), h2 = (i2 >> 10) & (HH - 1), b2 = i2 >> 20;
    int w3 = i3 & (WW - 1), h3 = (i3 >> 10) & (HH - 1), b3 = i3 >> 20;

    // 4 independent interpolations: ptxas batches the 16 gathers for max MLP.
    float r0 = bilin_one(imgs + (size_t)b0 * HW, h0, w0, d0.x, d0.y);
    float r1 = bilin_one(imgs + (size_t)b1 * HW, h1, w1, d1.x, d1.y);
    float r2 = bilin_one(imgs + (size_t)b2 * HW, h2, w2, d2.x, d2.y);
    float r3 = bilin_one(imgs + (size_t)b3 * HW, h3, w3, d3.x, d3.y);

    __stcs(out + i0, r0);
    __stcs(out + i1, r1);
    __stcs(out + i2, r2);
    __stcs(out + i3, r3);
}

extern "C" void kernel_launch(void* const* d_in, const int* in_sizes, int n_in,
                              void* d_out, int out_size) {
    const float* imgs = (const float*)d_in[0];
    const float* dvfs = (const float*)d_in[1];
    float* out = (float*)d_out;

    int total = out_size;                  // B*H*W
    int n_threads = total / 4;             // 4 px per thread
    int threads = 256;
    int blocks = (n_threads + threads - 1) / threads;
    bilinear_kernel<<<blocks, threads>>>(imgs, dvfs, out, total);
}